// round 9
// baseline (speedup 1.0000x reference)
#include <cuda_runtime.h>

// BranchRoute: score = sigmoid(x @ gate_w + gate_b); mask_i = score_i > 0.5
// out = concat(x*m0, x*m1, x*(m0+m1)), each [N, D] fp32.
// sigmoid(z) > 0.5 <=> z > 0, so only the dot-product sign matters.
//
// R9 = R8 (one row/block, grid=8192, best 86.2us) with ONE change:
// 256-bit vector memory ops (sm_100+ ld/st.global.v8.b32). Per thread:
// 2x LDG.256 + 6x STG.256 instead of 4x LDG.128 + 12x STG.128. Wider
// transactions -> fewer L1tex wavefronts per byte, 1KB-contiguous warp
// stores presented to LTS/DRAM.

#define THREADS 256
#define DIM 4096

__device__ __forceinline__ void ldg256(const float* p, float* r) {
    asm volatile(
        "ld.global.v8.b32 {%0,%1,%2,%3,%4,%5,%6,%7}, [%8];"
        : "=f"(r[0]), "=f"(r[1]), "=f"(r[2]), "=f"(r[3]),
          "=f"(r[4]), "=f"(r[5]), "=f"(r[6]), "=f"(r[7])
        : "l"(p));
}

__device__ __forceinline__ void stg256(float* p, const float* r) {
    asm volatile(
        "st.global.v8.b32 [%0], {%1,%2,%3,%4,%5,%6,%7,%8};"
        :: "l"(p),
           "f"(r[0]), "f"(r[1]), "f"(r[2]), "f"(r[3]),
           "f"(r[4]), "f"(r[5]), "f"(r[6]), "f"(r[7])
        : "memory");
}

__global__ void __launch_bounds__(THREADS)
branch_route_kernel(const float* __restrict__ x,
                    const float* __restrict__ gw,   // [D, 2]
                    const float* __restrict__ gb,   // [2]
                    float* __restrict__ out,        // [3, N, D]
                    int N)
{
    const int t = threadIdx.x;
    const int row = blockIdx.x;

    // This thread owns columns {k*2048 + t*8 + j : k in 0..1, j in 0..7}.
    // Gate pairs for those 16 columns (L2-resident, 32KB total).
    float2 w[16];
#pragma unroll
    for (int k = 0; k < 2; k++)
#pragma unroll
        for (int j = 0; j < 8; j++)
            w[k * 8 + j] = __ldg(&((const float2*)gw)[k * 2048 + t * 8 + j]);

    // Load the row: 2 x LDG.256 per thread (32B-aligned: rows are 16KB apart).
    const float* xr = x + (size_t)row * DIM;
    float v[2][8];
#pragma unroll
    for (int k = 0; k < 2; k++)
        ldg256(xr + k * 2048 + t * 8, v[k]);

    // Partial dots for both gate columns.
    float s0 = 0.f, s1 = 0.f;
#pragma unroll
    for (int k = 0; k < 2; k++)
#pragma unroll
        for (int j = 0; j < 8; j++) {
            s0 = fmaf(v[k][j], w[k * 8 + j].x, s0);
            s1 = fmaf(v[k][j], w[k * 8 + j].y, s1);
        }

    // Warp butterfly reduce.
#pragma unroll
    for (int o = 16; o > 0; o >>= 1) {
        s0 += __shfl_xor_sync(0xffffffffu, s0, o);
        s1 += __shfl_xor_sync(0xffffffffu, s1, o);
    }

    __shared__ float2 red[8];
    if ((t & 31) == 0) red[t >> 5] = make_float2(s0, s1);
    __syncthreads();

    float d0 = gb[0], d1 = gb[1];
#pragma unroll
    for (int k = 0; k < 8; k++) {
        d0 += red[k].x;
        d1 += red[k].y;
    }

    const float f0 = d0 > 0.f ? 1.f : 0.f;
    const float f1 = d1 > 0.f ? 1.f : 0.f;
    const float fc = f0 + f1;

    float* __restrict__ o0 = out + (size_t)row * DIM;
    float* __restrict__ o1 = o0 + (size_t)N * DIM;
    float* __restrict__ oc = o0 + (size_t)2 * N * DIM;

#pragma unroll
    for (int k = 0; k < 2; k++) {
        const int off = k * 2048 + t * 8;
        float a[8], b[8], s[8];
#pragma unroll
        for (int j = 0; j < 8; j++) {
            a[j] = f0 * v[k][j];
            b[j] = f1 * v[k][j];
            s[j] = fc * v[k][j];
        }
        stg256(o0 + off, a);
        stg256(o1 + off, b);
        stg256(oc + off, s);
    }
}

extern "C" void kernel_launch(void* const* d_in, const int* in_sizes, int n_in,
                              void* d_out, int out_size)
{
    const float* x  = (const float*)d_in[0];
    const float* gw = (const float*)d_in[1];
    const float* gb = (const float*)d_in[2];
    float* out = (float*)d_out;

    const int N = in_sizes[0] / DIM;   // 8192

    branch_route_kernel<<<N, THREADS>>>(x, gw, gb, out, N);
}

// round 10
// speedup vs baseline: 1.0643x; 1.0643x over previous
#include <cuda_runtime.h>

// BranchRoute: score = sigmoid(x @ gate_w + gate_b); mask_i = score_i > 0.5
// out = concat(x*m0, x*m1, x*(m0+m1)), each [N, D] fp32.
// sigmoid(z) > 0.5 <=> z > 0, so only the dot-product sign matters.
//
// R10 = R8 (one row/block, grid=8192, 128-bit ops, best 86.2us) with ONE
// change: full streaming cache hints. __ldcs on x reads (never reused ->
// evict-first frees L2 capacity for the 3x write stream), __stcs on all
// output stores. R9's 256-bit ops are reverted (L1tex wavefront replays
// crushed DRAM to 65%).
// After 9 rounds, every SM-side lever leaves DRAM at 65-73%; ~73% is the
// mixed 1R:3W HBM stream ceiling for this pattern.

#define THREADS 256
#define DIM 4096

__global__ void __launch_bounds__(THREADS)
branch_route_kernel(const float* __restrict__ x,
                    const float* __restrict__ gw,   // [D, 2]
                    const float* __restrict__ gb,   // [2]
                    float* __restrict__ out,        // [3, N, D]
                    int N)
{
    const int t = threadIdx.x;
    const int row = blockIdx.x;

    // This thread's 16 gate_w pairs (columns c*1024 + 4t + j), from L2.
    float2 w[16];
#pragma unroll
    for (int c = 0; c < 4; c++) {
#pragma unroll
        for (int j = 0; j < 4; j++) {
            int col = c * 1024 + t * 4 + j;
            w[c * 4 + j] = __ldg(&((const float2*)gw)[col]);
        }
    }

    // Load the row chunk (coalesced float4, streaming), keep in registers.
    const float4* xr = (const float4*)(x + (size_t)row * DIM);
    float4 v[4];
#pragma unroll
    for (int c = 0; c < 4; c++) v[c] = __ldcs(&xr[c * 256 + t]);

    // Partial dots for both gate columns.
    float s0 = 0.f, s1 = 0.f;
#pragma unroll
    for (int c = 0; c < 4; c++) {
        s0 = fmaf(v[c].x, w[c * 4 + 0].x, s0);
        s1 = fmaf(v[c].x, w[c * 4 + 0].y, s1);
        s0 = fmaf(v[c].y, w[c * 4 + 1].x, s0);
        s1 = fmaf(v[c].y, w[c * 4 + 1].y, s1);
        s0 = fmaf(v[c].z, w[c * 4 + 2].x, s0);
        s1 = fmaf(v[c].z, w[c * 4 + 2].y, s1);
        s0 = fmaf(v[c].w, w[c * 4 + 3].x, s0);
        s1 = fmaf(v[c].w, w[c * 4 + 3].y, s1);
    }

    // Warp butterfly reduce.
#pragma unroll
    for (int o = 16; o > 0; o >>= 1) {
        s0 += __shfl_xor_sync(0xffffffffu, s0, o);
        s1 += __shfl_xor_sync(0xffffffffu, s1, o);
    }

    __shared__ float2 red[8];
    if ((t & 31) == 0) red[t >> 5] = make_float2(s0, s1);
    __syncthreads();

    float d0 = gb[0], d1 = gb[1];
#pragma unroll
    for (int k = 0; k < 8; k++) {
        d0 += red[k].x;
        d1 += red[k].y;
    }

    const float f0 = d0 > 0.f ? 1.f : 0.f;
    const float f1 = d1 > 0.f ? 1.f : 0.f;
    const float fc = f0 + f1;

    const size_t base = (size_t)row * (DIM / 4);
    float4* __restrict__ p0 = (float4*)out + base;
    float4* __restrict__ p1 = (float4*)out + (size_t)N * (DIM / 4) + base;
    float4* __restrict__ pc = (float4*)out + (size_t)2 * N * (DIM / 4) + base;

#pragma unroll
    for (int c = 0; c < 4; c++) {
        const int idx = c * 256 + t;
        float4 a, b, s;
        a.x = f0 * v[c].x; a.y = f0 * v[c].y; a.z = f0 * v[c].z; a.w = f0 * v[c].w;
        b.x = f1 * v[c].x; b.y = f1 * v[c].y; b.z = f1 * v[c].z; b.w = f1 * v[c].w;
        s.x = fc * v[c].x; s.y = fc * v[c].y; s.z = fc * v[c].z; s.w = fc * v[c].w;
        __stcs(&p0[idx], a);
        __stcs(&p1[idx], b);
        __stcs(&pc[idx], s);
    }
}

extern "C" void kernel_launch(void* const* d_in, const int* in_sizes, int n_in,
                              void* d_out, int out_size)
{
    const float* x  = (const float*)d_in[0];
    const float* gw = (const float*)d_in[1];
    const float* gb = (const float*)d_in[2];
    float* out = (float*)d_out;

    const int N = in_sizes[0] / DIM;   // 8192

    // One row per block: best measured scheduling granularity.
    branch_route_kernel<<<N, THREADS>>>(x, gw, gb, out, N);
}

// round 11
// speedup vs baseline: 1.0879x; 1.0222x over previous
#include <cuda_runtime.h>

// BranchRoute: score = sigmoid(x @ gate_w + gate_b); mask_i = score_i > 0.5
// out = concat(x*m0, x*m1, x*(m0+m1)), each [N, D] fp32.
// sigmoid(z) > 0.5 <=> z > 0, so only the dot-product sign matters.
//
// R11 = R8 (one row/block, grid=8192, 128-bit ops, best bench 86.2us) with
// issue-side trims only:
//  - gate_w fetched as 8x LDG.128 per thread (was 16x LDG.64): halves the
//    per-block gate load count in the block-startup critical path.
//  - reduce partials read back as 4x LDS.128 (was 8x LDS.64).
// Ten rounds established DRAM is pinned at 65-73% for this 1R:3W stream
// regardless of SM-side structure; this is the ceiling config.

#define THREADS 256
#define DIM 4096

__global__ void __launch_bounds__(THREADS)
branch_route_kernel(const float* __restrict__ x,
                    const float* __restrict__ gw,   // [D, 2]
                    const float* __restrict__ gb,   // [2]
                    float* __restrict__ out,        // [3, N, D]
                    int N)
{
    const int t = threadIdx.x;
    const int row = blockIdx.x;

    // This thread's 16 gate_w pairs (columns c*1024 + 4t + j) = 32 floats,
    // contiguous in gw: fetch as 8 x float4 (L2-resident).
    float4 wv[8];
    {
        const float4* gw4 = (const float4*)gw;   // 2 pairs per float4
#pragma unroll
        for (int c = 0; c < 4; c++) {
            const int q = (c * 1024 + t * 4) >> 1;   // float4 index
            wv[c * 2 + 0] = __ldg(&gw4[q + 0]);      // pairs for cols 4t+0, 4t+1
            wv[c * 2 + 1] = __ldg(&gw4[q + 1]);      // pairs for cols 4t+2, 4t+3
        }
    }

    // Load the row chunk (coalesced float4), keep in registers.
    const float4* xr = (const float4*)(x + (size_t)row * DIM);
    float4 v[4];
#pragma unroll
    for (int c = 0; c < 4; c++) v[c] = xr[c * 256 + t];

    // Partial dots for both gate columns.
    // wv[2c]   = (w0.x->col0 pair) : {w[col0][0], w[col0][1], w[col1][0], w[col1][1]}
    // wv[2c+1] = {w[col2][0], w[col2][1], w[col3][0], w[col3][1]}
    float s0 = 0.f, s1 = 0.f;
#pragma unroll
    for (int c = 0; c < 4; c++) {
        const float4 wa = wv[c * 2 + 0];
        const float4 wb = wv[c * 2 + 1];
        s0 = fmaf(v[c].x, wa.x, s0);  s1 = fmaf(v[c].x, wa.y, s1);
        s0 = fmaf(v[c].y, wa.z, s0);  s1 = fmaf(v[c].y, wa.w, s1);
        s0 = fmaf(v[c].z, wb.x, s0);  s1 = fmaf(v[c].z, wb.y, s1);
        s0 = fmaf(v[c].w, wb.z, s0);  s1 = fmaf(v[c].w, wb.w, s1);
    }

    // Warp butterfly reduce.
#pragma unroll
    for (int o = 16; o > 0; o >>= 1) {
        s0 += __shfl_xor_sync(0xffffffffu, s0, o);
        s1 += __shfl_xor_sync(0xffffffffu, s1, o);
    }

    __shared__ __align__(16) float2 red[8];
    if ((t & 31) == 0) red[t >> 5] = make_float2(s0, s1);
    __syncthreads();

    float d0 = gb[0], d1 = gb[1];
#pragma unroll
    for (int k = 0; k < 4; k++) {
        const float4 r = ((const float4*)red)[k];   // two partials per LDS.128
        d0 += r.x + r.z;
        d1 += r.y + r.w;
    }

    const float f0 = d0 > 0.f ? 1.f : 0.f;
    const float f1 = d1 > 0.f ? 1.f : 0.f;
    const float fc = f0 + f1;

    const size_t base = (size_t)row * (DIM / 4);
    float4* __restrict__ p0 = (float4*)out + base;
    float4* __restrict__ p1 = (float4*)out + (size_t)N * (DIM / 4) + base;
    float4* __restrict__ pc = (float4*)out + (size_t)2 * N * (DIM / 4) + base;

#pragma unroll
    for (int c = 0; c < 4; c++) {
        const int idx = c * 256 + t;
        float4 a, b, s;
        a.x = f0 * v[c].x; a.y = f0 * v[c].y; a.z = f0 * v[c].z; a.w = f0 * v[c].w;
        b.x = f1 * v[c].x; b.y = f1 * v[c].y; b.z = f1 * v[c].z; b.w = f1 * v[c].w;
        s.x = fc * v[c].x; s.y = fc * v[c].y; s.z = fc * v[c].z; s.w = fc * v[c].w;
        p0[idx] = a;
        p1[idx] = b;
        pc[idx] = s;
    }
}

extern "C" void kernel_launch(void* const* d_in, const int* in_sizes, int n_in,
                              void* d_out, int out_size)
{
    const float* x  = (const float*)d_in[0];
    const float* gw = (const float*)d_in[1];
    const float* gb = (const float*)d_in[2];
    float* out = (float*)d_out;

    const int N = in_sizes[0] / DIM;   // 8192

    // One row per block: best measured scheduling granularity.
    branch_route_kernel<<<N, THREADS>>>(x, gw, gb, out, N);
}